// round 17
// baseline (speedup 1.0000x reference)
#include <cuda_runtime.h>
#include <math.h>
#include <stdint.h>

// Problem constants (fixed shapes for this problem instance)
#define S_LEN  1024
#define DM     4096
#define NH     32
#define HD     128
#define CACHE  2048
#define TTOT   (CACHE + S_LEN)   // 3072 total kv positions

// Scratch (device globals: allocation-free rule)
__device__ float g_xn[S_LEN * DM];
__device__ float g_q [S_LEN * DM];
__device__ float g_k [S_LEN * DM];
__device__ float g_v [S_LEN * DM];
__device__ float g_at[S_LEN * DM];

// ---------------------------------------------------------------------------
// Common tensor-core helpers
// ---------------------------------------------------------------------------
__device__ __forceinline__ uint32_t f2tf32(float x) {
    uint32_t r;
    asm("cvt.rna.tf32.f32 %0, %1;" : "=r"(r) : "f"(x));
    return r;
}
__device__ __forceinline__ uint32_t u2tf32(uint32_t x) {
    uint32_t r;
    asm("cvt.rna.tf32.f32 %0, %1;" : "=r"(r) : "r"(x));
    return r;
}

__device__ __forceinline__ void mma_tf32(float c[4], const uint32_t a[4], const uint32_t b[2]) {
    asm volatile(
        "mma.sync.aligned.m16n8k8.row.col.f32.tf32.tf32.f32 "
        "{%0,%1,%2,%3}, {%4,%5,%6,%7}, {%8,%9}, {%0,%1,%2,%3};"
        : "+f"(c[0]), "+f"(c[1]), "+f"(c[2]), "+f"(c[3])
        : "r"(a[0]), "r"(a[1]), "r"(a[2]), "r"(a[3]), "r"(b[0]), "r"(b[1]));
}

__device__ __forceinline__ void ldsm4(uint32_t r[4], uint32_t addr) {
    asm volatile("ldmatrix.sync.aligned.m8n8.x4.shared.b16 {%0,%1,%2,%3}, [%4];"
        : "=r"(r[0]), "=r"(r[1]), "=r"(r[2]), "=r"(r[3]) : "r"(addr));
}

__device__ __forceinline__ void cp16(uint32_t dst, const void* src) {
    asm volatile("cp.async.cg.shared.global [%0], [%1], 16;" :: "r"(dst), "l"(src));
}
#define CP_COMMIT()  asm volatile("cp.async.commit_group;")
#define CP_WAIT0()   asm volatile("cp.async.wait_group 0;")
#define CP_WAIT1()   asm volatile("cp.async.wait_group 1;")

#define BAR_PAIR(id) asm volatile("bar.sync %0, 64;" :: "r"(id) : "memory")

// ---------------------------------------------------------------------------
// RMSNorm: one block per row (4096 elems), 256 threads. Emits rna tf32.
// ---------------------------------------------------------------------------
__global__ void rmsnorm_kernel(const float* __restrict__ xs,
                               const float* __restrict__ w)
{
    const int row = blockIdx.x;
    const int tid = threadIdx.x;
    const float* x = xs + (size_t)row * DM;
    float* y = g_xn + (size_t)row * DM;

    float ss = 0.f;
#pragma unroll
    for (int i = 0; i < 4; i++) {
        float4 v = *(const float4*)(x + (i * 256 + tid) * 4);
        ss += v.x * v.x + v.y * v.y + v.z * v.z + v.w * v.w;
    }
#pragma unroll
    for (int off = 16; off; off >>= 1)
        ss += __shfl_xor_sync(0xffffffffu, ss, off);

    __shared__ float red[8];
    __shared__ float s_inv;
    if ((tid & 31) == 0) red[tid >> 5] = ss;
    __syncthreads();
    if (tid == 0) {
        float t = 0.f;
#pragma unroll
        for (int i = 0; i < 8; i++) t += red[i];
        s_inv = rsqrtf(t / (float)DM + 1e-6f);
    }
    __syncthreads();
    const float inv = s_inv;
#pragma unroll
    for (int i = 0; i < 4; i++) {
        int base = (i * 256 + tid) * 4;
        float4 v = *(const float4*)(x + base);
        float4 g = *(const float4*)(w + base);
        uint4 u;
        u.x = f2tf32(v.x * inv * g.x);
        u.y = f2tf32(v.y * inv * g.y);
        u.z = f2tf32(v.z * inv * g.z);
        u.w = f2tf32(v.w * inv * g.w);
        *(uint4*)(y + base) = u;
    }
}

// ---------------------------------------------------------------------------
// TF32 tensor-core GEMM (NT): tile 128x128x32, 3-stage cp.async, ldmatrix
// fragments, stride 36. B raw fp32, rounded in registers. A pre-rounded.
// FUSED: grid.x covers q|k|v thirds (plain stores; V rounded later in flash).
// ---------------------------------------------------------------------------
#define GSTR 36
#define ATW  (128 * GSTR)
#define STW  (2 * ATW)
#define NST  3
#define GEMM_SMEM_BYTES (NST * STW * 4)   // 110592 B

template <bool FUSED>
__global__ void __launch_bounds__(256, 2)
sgemm_tc(const float* __restrict__ A,
         const float* __restrict__ B0, const float* __restrict__ B1,
         const float* __restrict__ B2,
         float* __restrict__ C0, int N, int K)
{
    extern __shared__ uint32_t gsm[];
    const uint32_t sbase = (uint32_t)__cvta_generic_to_shared(gsm);

    const int tid  = threadIdx.x;
    const int lane = tid & 31;
    const int warp = tid >> 5;
    const int g    = lane >> 2;
    const int tig  = lane & 3;
    const int m_base = (warp >> 2) * 64;
    const int n_base = (warp & 3) * 32;

    const float* B = B0;
    float* C = C0;
    int bxx = blockIdx.x;
    if (FUSED) {
        const int third = blockIdx.x >> 5;       // 0:q 1:k 2:v
        bxx = blockIdx.x & 31;
        if (third == 1)      { B = B1; C = g_k; }
        else if (third == 2) { B = B2; C = g_v; }
    }

    const int r0 = tid >> 3;
    const int c0 = (tid & 7) << 2;
    const float* Ag = A + (size_t)(blockIdx.y * 128 + r0) * K + c0;
    const float* Bg = B + (size_t)(bxx * 128 + r0) * K + c0;
    const uint32_t d0 = (uint32_t)(r0 * GSTR + c0) * 4;
    const size_t gstep = (size_t)32 * K;
    const uint32_t sstep = (uint32_t)(32 * GSTR) * 4;

    auto issue = [&](int kt) {
        const uint32_t st = sbase + (uint32_t)(kt % NST) * (STW * 4);
        const int ko = kt << 5;
        const float* a = Ag + ko;
        const float* b = Bg + ko;
#pragma unroll
        for (int it = 0; it < 4; it++) {
            cp16(st + d0 + it * sstep, a + it * gstep);
            cp16(st + ATW * 4 + d0 + it * sstep, b + it * gstep);
        }
        CP_COMMIT();
    };

    float c[4][4][4];
#pragma unroll
    for (int mt = 0; mt < 4; mt++)
#pragma unroll
        for (int nt = 0; nt < 4; nt++)
#pragma unroll
            for (int i = 0; i < 4; i++) c[mt][nt][i] = 0.f;

    issue(0); issue(1);

    const int arow  = m_base + (lane & 15);
    const int acolh = (lane >> 2) & 4;
    const int brow  = n_base + (lane & 7) + ((lane >> 1) & 8);
    const int bcolh = (lane >> 1) & 4;

    const int KT = K >> 5;
    for (int kt = 0; kt < KT; kt++) {
        if (kt + 1 < KT) { CP_WAIT1(); } else { CP_WAIT0(); }
        __syncthreads();
        if (kt + 2 < KT) issue(kt + 2);

        const uint32_t tA = sbase + (uint32_t)(kt % NST) * (STW * 4);
        const uint32_t tB = tA + ATW * 4;
#pragma unroll
        for (int kk = 0; kk < 4; kk++) {
            uint32_t a[4][4], b[2][4];
#pragma unroll
            for (int mt = 0; mt < 4; mt++)
                ldsm4(a[mt], tA + (uint32_t)((arow + mt * 16) * GSTR + kk * 8 + acolh) * 4);
            ldsm4(b[0], tB + (uint32_t)(brow * GSTR + kk * 8 + bcolh) * 4);
            ldsm4(b[1], tB + (uint32_t)((brow + 16) * GSTR + kk * 8 + bcolh) * 4);
#pragma unroll
            for (int i = 0; i < 4; i++) {
                b[0][i] = u2tf32(b[0][i]);
                b[1][i] = u2tf32(b[1][i]);
            }
#pragma unroll
            for (int mt = 0; mt < 4; mt++)
#pragma unroll
                for (int nt = 0; nt < 4; nt++) {
                    uint32_t bb[2] = { b[nt >> 1][(nt & 1) * 2],
                                       b[nt >> 1][(nt & 1) * 2 + 1] };
                    mma_tf32(c[mt][nt], a[mt], bb);
                }
        }
    }

    const int crow = blockIdx.y * 128 + m_base + g;
    const int ccol = bxx * 128 + n_base + 2 * tig;
#pragma unroll
    for (int mt = 0; mt < 4; mt++) {
#pragma unroll
        for (int nt = 0; nt < 4; nt++) {
            const int row = crow + mt * 16;
            const int col = ccol + nt * 8;
            *(float2*)(C + (size_t)row * N + col) =
                make_float2(c[mt][nt][0], c[mt][nt][1]);
            *(float2*)(C + (size_t)(row + 8) * N + col) =
                make_float2(c[mt][nt][2], c[mt][nt][3]);
        }
    }
}

// ---------------------------------------------------------------------------
// Merged RoPE: q AND k in-place (raw fp32; rounding happens in flash regs).
// ---------------------------------------------------------------------------
__global__ void rope_qk_kernel()
{
    int idx = blockIdx.x * blockDim.x + threadIdx.x;
    int i = idx & 63;
    int h = (idx >> 6) & (NH - 1);
    int s = idx >> 11;

    float pos = (float)(s + CACHE);
    float inv_freq = exp2f(-(float)i * (13.287712379549449f / 64.f));
    float ang = pos * inv_freq;
    float sn, cs;
    sincosf(ang, &sn, &cs);

    const size_t off = ((size_t)(s * NH + h) * HD) + i;
    {
        float* p = g_q + off;
        float x1 = p[0];
        float x2 = p[64];
        p[0]  = x1 * cs - x2 * sn;
        p[64] = x2 * cs + x1 * sn;
    }
    {
        float* p = g_k + off;
        float x1 = p[0];
        float x2 = p[64];
        p[0]  = x1 * cs - x2 * sn;
        p[64] = x2 * cs + x1 * sn;
    }
}

// ---------------------------------------------------------------------------
// Tensor-core flash attention, 32-key tiles, 2 CTAs/SM, register softmax,
// register-resident Q (proven R16). NEW: reads RAW cache_k/cache_v and raw
// g_k/g_v directly (per-tile pointer select; tiles never straddle the
// boundary); K and V rounded to tf32 IN REGISTERS (bit-identical to the
// old pre-converted buffers) — the convert pass is gone.
// ---------------------------------------------------------------------------
#define KQSTR 132
#define VSTR  136
#define PSTR  36
#define TKEY  32           // keys per tile

#define QS_WORDS (64 * KQSTR)
#define KS_WORDS (TKEY * KQSTR)
#define VS_WORDS (TKEY * VSTR)
#define PS_WORDS (64 * PSTR)

#define FLASH_SMEM_WORDS (QS_WORDS + 2*KS_WORDS + 2*VS_WORDS + PS_WORDS + 384)
#define FLASH_SMEM_BYTES (FLASH_SMEM_WORDS * 4)   // ~113.2 KB

__global__ void __launch_bounds__(256, 2)
flash_tc_kernel(const float* __restrict__ cache_k,
                const float* __restrict__ cache_v)
{
    extern __shared__ uint32_t fsm[];
    uint32_t* Qs  = fsm;
    uint32_t* Ks0 = Qs  + QS_WORDS;
    uint32_t* Ks1 = Ks0 + KS_WORDS;
    uint32_t* Vs0 = Ks1 + KS_WORDS;
    uint32_t* Vs1 = Vs0 + VS_WORDS;
    uint32_t* Ps  = Vs1 + VS_WORDS;
    float* m_s = (float*)(Ps + PS_WORDS);
    float* l_s = m_s + 64;
    float* hm  = l_s + 64;    // [2][64] partial row max per warp-half
    float* hs  = hm + 128;    // [2][64] partial row sum per warp-half
    uint32_t* PsU = Ps;

    const int h  = blockIdx.x;
    const int qt = (S_LEN / 64 - 1) - blockIdx.y;
    const int tid = threadIdx.x;
    const int lane = tid & 31;
    const int warp = tid >> 5;
    const int g    = lane >> 2;
    const int tig  = lane & 3;
    const int wr   = warp >> 1;
    const int wc   = warp & 1;
    const int m0   = wr * 16;

    const uint32_t qs_a  = (uint32_t)__cvta_generic_to_shared(Qs);
    const uint32_t ks0_a = (uint32_t)__cvta_generic_to_shared(Ks0);
    const uint32_t ks1_a = (uint32_t)__cvta_generic_to_shared(Ks1);
    const uint32_t vs0_a = (uint32_t)__cvta_generic_to_shared(Vs0);
    const uint32_t vs1_a = (uint32_t)__cvta_generic_to_shared(Vs1);
    const uint32_t ps_a  = (uint32_t)__cvta_generic_to_shared(Ps);

    const float qscale = 0.08838834764831845f;
#pragma unroll
    for (int it = 0; it < 8; it++) {
        int idx = it * 256 + tid;
        int r = idx >> 5;
        int c = (idx & 31) << 2;
        float4 v = *(const float4*)(g_q + (size_t)(qt * 64 + r) * DM + h * HD + c);
        uint4 u;
        u.x = f2tf32(v.x * qscale);
        u.y = f2tf32(v.y * qscale);
        u.z = f2tf32(v.z * qscale);
        u.w = f2tf32(v.w * qscale);
        *(uint4*)&Qs[r * KQSTR + c] = u;
    }
    if (tid < 64) { m_s[tid] = -1e30f; l_s[tid] = 0.f; }

    // Raw sources; tiles never straddle the cache/new boundary (32 | 2048).
    auto issue_kv = [&](int kt, int b) {
        const int t0 = kt * TKEY;
        const uint32_t ka = b ? ks1_a : ks0_a;
        const uint32_t va = b ? vs1_a : vs0_a;
        const float* kb;
        const float* vb;
        if (t0 < CACHE) { kb = cache_k; vb = cache_v; }
        else            { kb = g_k - (size_t)CACHE * DM; vb = g_v - (size_t)CACHE * DM; }
#pragma unroll
        for (int it = 0; it < 4; it++) {
            int idx = it * 256 + tid;
            int r = idx >> 5;
            int c = (idx & 31) << 2;
            size_t off = (size_t)(t0 + r) * DM + h * HD + c;
            cp16(ka + (r * KQSTR + c) * 4, kb + off);
            cp16(va + (r * VSTR  + c) * 4, vb + off);
        }
        CP_COMMIT();
    };

    issue_kv(0, 0);

    const int arow  = m0 + (lane & 15);
    const int acolh = (lane >> 2) & 4;
    const int brow  = wc * 16 + (lane & 7) + ((lane >> 1) & 8);   // 0..31
    const int bcolh = (lane >> 1) & 4;
    const int barid = 1 + wr;
    const int r0 = m0 + g, r1 = m0 + g + 8;

    // ---- Preload ALL Q fragments into registers (once per block) ----
    __syncthreads();
    uint32_t qf[16][4];
#pragma unroll
    for (int ks = 0; ks < 16; ks++)
        ldsm4(qf[ks], qs_a + (uint32_t)(arow * KQSTR + ks * 8 + acolh) * 4);

    float oacc[8][4];
#pragma unroll
    for (int nt = 0; nt < 8; nt++)
#pragma unroll
        for (int i = 0; i < 4; i++) oacc[nt][i] = 0.f;

    const int ntiles = 66 + 2 * qt;        // (CACHE + (qt+1)*64) / 32
    const int maskb0 = -(CACHE + qt * 64); // t0 + col + maskb0 = rel col
    int p = 0;
    for (int kt = 0; kt < ntiles; kt++) {
        CP_WAIT0();
        __syncthreads();
        if (kt + 1 < ntiles) issue_kv(kt + 1, p ^ 1);

        const uint32_t ka = p ? ks1_a : ks0_a;
        const uint32_t* Vc = p ? Vs1 : Vs0;

        // ---- S = Q K^T (warp tile 16x16), Q from regs, K cvt in regs ----
        float sacc[2][4];
#pragma unroll
        for (int nt = 0; nt < 2; nt++)
#pragma unroll
            for (int i = 0; i < 4; i++) sacc[nt][i] = 0.f;

#pragma unroll
        for (int ks = 0; ks < 16; ks++) {
            const int k0 = ks * 8;
            uint32_t b[4];
            ldsm4(b, ka + (uint32_t)(brow * KQSTR + k0 + bcolh) * 4);
            b[0] = u2tf32(b[0]); b[1] = u2tf32(b[1]);
            b[2] = u2tf32(b[2]); b[3] = u2tf32(b[3]);
            {
                uint32_t bb0[2] = { b[0], b[1] };
                uint32_t bb1[2] = { b[2], b[3] };
                mma_tf32(sacc[0], qf[ks], bb0);
                mma_tf32(sacc[1], qf[ks], bb1);
            }
        }

        // ---- mask + partial row max in registers ----
        const bool domask = (kt >= ntiles - 2);
        const int mrel = kt * TKEY + maskb0;
        float pm0 = -1e30f, pm1 = -1e30f;
#pragma unroll
        for (int nt = 0; nt < 2; nt++) {
            const int col = wc * 16 + nt * 8 + 2 * tig;
            if (domask) {
                const int c0r = mrel + col, c1r = mrel + col + 1;
                if (c0r > r0) sacc[nt][0] = -1e30f;
                if (c1r > r0) sacc[nt][1] = -1e30f;
                if (c0r > r1) sacc[nt][2] = -1e30f;
                if (c1r > r1) sacc[nt][3] = -1e30f;
            }
            pm0 = fmaxf(pm0, fmaxf(sacc[nt][0], sacc[nt][1]));
            pm1 = fmaxf(pm1, fmaxf(sacc[nt][2], sacc[nt][3]));
        }
        pm0 = fmaxf(pm0, __shfl_xor_sync(0xffffffffu, pm0, 1));
        pm0 = fmaxf(pm0, __shfl_xor_sync(0xffffffffu, pm0, 2));
        pm1 = fmaxf(pm1, __shfl_xor_sync(0xffffffffu, pm1, 1));
        pm1 = fmaxf(pm1, __shfl_xor_sync(0xffffffffu, pm1, 2));
        if (tig == 0) {
            hm[wc * 64 + r0] = pm0;
            hm[wc * 64 + r1] = pm1;
        }
        BAR_PAIR(barid);

        // ---- combine maxes, exp in registers, store tf32 P ----
        const float mold0 = m_s[r0], mold1 = m_s[r1];
        const float mx0 = fmaxf(fmaxf(hm[r0], hm[64 + r0]), mold0);
        const float mx1 = fmaxf(fmaxf(hm[r1], hm[64 + r1]), mold1);
        const float al0 = __expf(mold0 - mx0);
        const float al1 = __expf(mold1 - mx1);
        float ps0 = 0.f, ps1 = 0.f;
#pragma unroll
        for (int nt = 0; nt < 2; nt++) {
            const int col = wc * 16 + nt * 8 + 2 * tig;
            float e0 = __expf(sacc[nt][0] - mx0);
            float e1 = __expf(sacc[nt][1] - mx0);
            float e2 = __expf(sacc[nt][2] - mx1);
            float e3 = __expf(sacc[nt][3] - mx1);
            ps0 += e0 + e1;
            ps1 += e2 + e3;
            uint32_t* d0 = &PsU[r0 * PSTR + col];
            uint32_t* d1 = &PsU[r1 * PSTR + col];
            d0[0] = f2tf32(e0); d0[1] = f2tf32(e1);
            d1[0] = f2tf32(e2); d1[1] = f2tf32(e3);
        }
        ps0 += __shfl_xor_sync(0xffffffffu, ps0, 1);
        ps0 += __shfl_xor_sync(0xffffffffu, ps0, 2);
        ps1 += __shfl_xor_sync(0xffffffffu, ps1, 1);
        ps1 += __shfl_xor_sync(0xffffffffu, ps1, 2);
        if (tig == 0) {
            hs[wc * 64 + r0] = ps0;
            hs[wc * 64 + r1] = ps1;
        }
        BAR_PAIR(barid);
        if (wc == 0 && tig == 0) {
            l_s[r0] = l_s[r0] * al0 + hs[r0] + hs[64 + r0];
            l_s[r1] = l_s[r1] * al1 + hs[r1] + hs[64 + r1];
            m_s[r0] = mx0;
            m_s[r1] = mx1;
        }

        // ---- rescale O (local alpha), then O += P V (V cvt in regs) ----
        {
#pragma unroll
            for (int nt = 0; nt < 8; nt++) {
                oacc[nt][0] *= al0; oacc[nt][1] *= al0;
                oacc[nt][2] *= al1; oacc[nt][3] *= al1;
            }
#pragma unroll
            for (int ks = 0; ks < 4; ks++) {
                const int k0 = ks * 8;
                uint32_t a[4];
                ldsm4(a, ps_a + (uint32_t)(arow * PSTR + k0 + acolh) * 4);
                const uint32_t* V0 = Vc + (k0 + tig) * VSTR + wc * 64 + g;
                const uint32_t* V1 = V0 + 4 * VSTR;
#pragma unroll
                for (int nt = 0; nt < 8; nt++) {
                    uint32_t b[2];
                    b[0] = u2tf32(V0[nt * 8]);
                    b[1] = u2tf32(V1[nt * 8]);
                    mma_tf32(oacc[nt], a, b);
                }
            }
        }
        p ^= 1;
    }

    __syncthreads();
    const float ilo = 1.f / l_s[m0 + g];
    const float ihi = 1.f / l_s[m0 + g + 8];
    const int grow = qt * 64 + m0 + g;
#pragma unroll
    for (int nt = 0; nt < 8; nt++) {
        const int col = h * HD + wc * 64 + nt * 8 + 2 * tig;
        uint32_t* d0 = (uint32_t*)(g_at + (size_t)grow * DM + col);
        uint32_t* d1 = (uint32_t*)(g_at + (size_t)(grow + 8) * DM + col);
        d0[0] = f2tf32(oacc[nt][0] * ilo);
        d0[1] = f2tf32(oacc[nt][1] * ilo);
        d1[0] = f2tf32(oacc[nt][2] * ihi);
        d1[1] = f2tf32(oacc[nt][3] * ihi);
    }
}

// ---------------------------------------------------------------------------
// Launch
// ---------------------------------------------------------------------------
extern "C" void kernel_launch(void* const* d_in, const int* in_sizes, int n_in,
                              void* d_out, int out_size)
{
    (void)in_sizes; (void)n_in; (void)out_size;
    const float* xs      = (const float*)d_in[0];
    const float* cache_k = (const float*)d_in[1];
    const float* cache_v = (const float*)d_in[2];
    const float* norm_w  = (const float*)d_in[3];
    const float* wq      = (const float*)d_in[4];
    const float* wk      = (const float*)d_in[5];
    const float* wv      = (const float*)d_in[6];
    const float* wo      = (const float*)d_in[7];
    float* out = (float*)d_out;

    float *p_xn, *p_q, *p_at;
    cudaGetSymbolAddress((void**)&p_xn, g_xn);
    cudaGetSymbolAddress((void**)&p_q,  g_q);
    cudaGetSymbolAddress((void**)&p_at, g_at);

    cudaFuncSetAttribute((const void*)&sgemm_tc<true>,
                         cudaFuncAttributeMaxDynamicSharedMemorySize,
                         GEMM_SMEM_BYTES);
    cudaFuncSetAttribute((const void*)&sgemm_tc<false>,
                         cudaFuncAttributeMaxDynamicSharedMemorySize,
                         GEMM_SMEM_BYTES);
    cudaFuncSetAttribute((const void*)&flash_tc_kernel,
                         cudaFuncAttributeMaxDynamicSharedMemorySize,
                         FLASH_SMEM_BYTES);

    // 1) RMSNorm (emits tf32-rounded xn)
    rmsnorm_kernel<<<S_LEN, 256>>>(xs, norm_w);

    // 2) Fused QKV projection (raw weights, B rounded in-register):
    //    q -> g_q, k -> g_k, v -> g_v (all raw fp32 outputs).
    {
        dim3 gq(3 * DM / 128, S_LEN / 128);   // (96, 8)
        sgemm_tc<true><<<gq, 256, GEMM_SMEM_BYTES>>>(
            p_xn, wq, wk, wv, p_q, DM, DM);
    }

    // 3) Merged RoPE: q and k in-place (raw)
    rope_qk_kernel<<<(S_LEN * NH * 64) / 256, 256>>>();

    // 4) Tensor-core flash attention (raw K/V sources, cvt in registers)
    flash_tc_kernel<<<dim3(NH, S_LEN / 64), 256, FLASH_SMEM_BYTES>>>(cache_k, cache_v);

    // 5) Output projection -> d_out (raw wo, B rounded in-register)
    {
        dim3 gg(DM / 128, S_LEN / 128);
        sgemm_tc<false><<<gg, 256, GEMM_SMEM_BYTES>>>(
            p_at, wo, nullptr, nullptr, out, DM, DM);
    }
}